// round 9
// baseline (speedup 1.0000x reference)
#include <cuda_runtime.h>
#include <cstdint>
#include <cstddef>

// Net_quantize: fused MFL recurrence + LSQ fake-quant + 2 quantized linear layers.
// TWO rows per thread (ILP-2): the two independent recurrence chains interleave,
// filling the rcp.approx latency from within the warp; w1p weight loads are
// shared between both rows. x staged via cp.async.cg, double-buffered,
// [quad][row] float4 layout (conflict-free STS/LDS).
//
// 256 threads / 512 rows per block, 16 chunks x 8 cols, grid = M/512 = 512.

#define THREADS 256
#define RPB     512
#define NCOLS   128
#define NCHUNK  16            // 8 cols per chunk
#define QPC     2             // float4 quads per chunk per row

__device__ __forceinline__ void cp_async16(uint32_t saddr, const void* gptr) {
    asm volatile("cp.async.cg.shared.global [%0], [%1], 16;"
                 :: "r"(saddr), "l"(gptr) : "memory");
}
__device__ __forceinline__ void cp_commit() {
    asm volatile("cp.async.commit_group;" ::: "memory");
}
template <int N>
__device__ __forceinline__ void cp_wait() {
    asm volatile("cp.async.wait_group %0;" :: "n"(N) : "memory");
}

__global__ __launch_bounds__(THREADS, 4)
void net_quant_kernel(const float* __restrict__ x,
                      const float* __restrict__ p_alpha,
                      const float* __restrict__ p_beta,
                      const float* __restrict__ p_a1,
                      const float* __restrict__ p_a2,
                      const float* __restrict__ p_a3,
                      const float* __restrict__ W1,
                      const float* __restrict__ b1,
                      const float* __restrict__ p_wa1,
                      const float* __restrict__ W2,
                      const float* __restrict__ b2,
                      const float* __restrict__ p_wa2,
                      float* __restrict__ out)
{
    // [buf][quad][row] -> LDS.128 at row=tid: lane r hits banks 4r%32 (clean);
    // cp.async writes: 8-lane phase covers 8 consecutive rows (clean).
    __shared__ float4 xsq[2][QPC][RPB];   // 32 KiB
    __shared__ int    w1p[32 * 16];       // [kc][j], kc = k/4
    __shared__ int    w2p[10 * 4];        // [j][c]
    __shared__ float  b1s[16];
    __shared__ float  b2s[10];

    const int tid  = threadIdx.x;
    const int row0 = blockIdx.x * RPB;

    // staging lane: thread stages (row_s + 128*it, quad q_s), it = 0..3
    const int row_s = tid >> 1, q_s = tid & 1;
    const float* gsrc = x + (size_t)(row0 + row_s) * NCOLS + q_s * 4;
    const uint32_t xs_base = (uint32_t)__cvta_generic_to_shared(xsq);
    // byte offset of (q_s, row_s) within one buffer
    const uint32_t soff = (uint32_t)(q_s * RPB + row_s) * 16u;
    const uint32_t BUFB = QPC * RPB * 16u;     // bytes per buffer

    // ---- issue chunk 0 staging immediately ----
    {
        const uint32_t b = xs_base + soff;
        cp_async16(b,              gsrc);
        cp_async16(b + 128 * 16u,  gsrc + (size_t)128 * NCOLS);
        cp_async16(b + 256 * 16u,  gsrc + (size_t)256 * NCOLS);
        cp_async16(b + 384 * 16u,  gsrc + (size_t)384 * NCOLS);
        cp_commit();
    }

    // loop-live scalars only
    const float alpha  = p_alpha[0];
    const float beta   = p_beta[0];
    const float inv_a1 = 1.0f / p_a1[0];

    // ---- quantize + pack W1 (16x128), layout [kc][j] ----
    {
        const float inv_wa1 = 1.0f / p_wa1[0];
        for (int i = tid; i < 512; i += THREADS) {
            const int kc = i >> 4, j = i & 15;
            unsigned v = 0;
#pragma unroll
            for (int b = 0; b < 4; ++b) {
                float t = W1[j * 128 + kc * 4 + b] * inv_wa1;
                int q;
                asm("cvt.rni.sat.s8.f32 %0, %1;" : "=r"(q) : "f"(t));
                v = __byte_perm(v, (unsigned)q, 0x4321);
            }
            w1p[i] = (int)v;
        }
    }
    // ---- quantize + pack W2 (10x16), preload biases ----
    if (tid < 40) {
        const float inv_wa2 = 1.0f / p_wa2[0];
        const int j = tid >> 2, c = tid & 3;
        unsigned v = 0;
#pragma unroll
        for (int b = 0; b < 4; ++b) {
            float t = W2[j * 16 + c * 4 + b] * inv_wa2;
            int q;
            asm("cvt.rni.sat.s8.f32 %0, %1;" : "=r"(q) : "f"(t));
            v = __byte_perm(v, (unsigned)q, 0x4321);
        }
        w2p[tid] = (int)v;
    }
    if (tid >= 64 && tid < 80) b1s[tid - 64] = b1[tid - 64];
    if (tid >= 96 && tid < 106) b2s[tid - 96] = b2[tid - 96];
    // (ordered by the first pipeline __syncthreads)

    // ---- two independent recurrences per thread ----
    float wA = 1.0f, wB = 1.0f;
    unsigned hpA = 0, hpB = 0;
    int accA[16], accB[16];
#pragma unroll
    for (int j = 0; j < 16; ++j) { accA[j] = 0; accB[j] = 0; }

    const int rowA = tid;          // compute rows
    const int rowB = tid + 256;

#pragma unroll
    for (int c = 0; c < NCHUNK; ++c) {
        if (c < NCHUNK - 1) {
            const uint32_t b = xs_base + (((c + 1) & 1) ? BUFB : 0u) + soff;
            const float* g = gsrc + (c + 1) * 8;
            cp_async16(b,             g);
            cp_async16(b + 128 * 16u, g + (size_t)128 * NCOLS);
            cp_async16(b + 256 * 16u, g + (size_t)256 * NCOLS);
            cp_async16(b + 384 * 16u, g + (size_t)384 * NCOLS);
            cp_commit();
            cp_wait<1>();          // chunk c complete (c+1 in flight)
        } else {
            cp_wait<0>();
        }
        __syncthreads();

        const int buf = c & 1;
#pragma unroll
        for (int g = 0; g < QPC; ++g) {
            const float4 vA = xsq[buf][g][rowA];
            const float4 vB = xsq[buf][g][rowB];
            const float xeA[4] = {vA.x, vA.y, vA.z, vA.w};
            const float xeB[4] = {vB.x, vB.y, vB.z, vB.w};
#pragma unroll
            for (int b = 0; b < 4; ++b) {
                // --- row A step ---
                {
                    const float t = wA * inv_a1;
                    int hq;
                    asm("cvt.rni.sat.s8.f32 %0, %1;" : "=r"(hq) : "f"(t));
                    hpA = __byte_perm(hpA, (unsigned)hq, 0x4321);
                    const float t2 = __fmaf_rn(-beta, xeA[b], wA);
                    float r;
                    asm("rcp.approx.f32 %0, %1;" : "=f"(r) : "f"(wA));
                    wA = __fmaf_rn(alpha, r, t2);
                }
                // --- row B step (independent: fills A's rcp latency) ---
                {
                    const float t = wB * inv_a1;
                    int hq;
                    asm("cvt.rni.sat.s8.f32 %0, %1;" : "=r"(hq) : "f"(t));
                    hpB = __byte_perm(hpB, (unsigned)hq, 0x4321);
                    const float t2 = __fmaf_rn(-beta, xeB[b], wB);
                    float r;
                    asm("rcp.approx.f32 %0, %1;" : "=f"(r) : "f"(wB));
                    wB = __fmaf_rn(alpha, r, t2);
                }
            }
            // shared weight loads, dp4a for both rows
            const int kc = c * QPC + g;
            const int4* wp = reinterpret_cast<const int4*>(&w1p[kc * 16]);
            {
                const int4 w0 = wp[0];
                accA[0] = __dp4a((int)hpA, w0.x, accA[0]);
                accB[0] = __dp4a((int)hpB, w0.x, accB[0]);
                accA[1] = __dp4a((int)hpA, w0.y, accA[1]);
                accB[1] = __dp4a((int)hpB, w0.y, accB[1]);
                accA[2] = __dp4a((int)hpA, w0.z, accA[2]);
                accB[2] = __dp4a((int)hpB, w0.z, accB[2]);
                accA[3] = __dp4a((int)hpA, w0.w, accA[3]);
                accB[3] = __dp4a((int)hpB, w0.w, accB[3]);
            }
            {
                const int4 w1v = wp[1];
                accA[4] = __dp4a((int)hpA, w1v.x, accA[4]);
                accB[4] = __dp4a((int)hpB, w1v.x, accB[4]);
                accA[5] = __dp4a((int)hpA, w1v.y, accA[5]);
                accB[5] = __dp4a((int)hpB, w1v.y, accB[5]);
                accA[6] = __dp4a((int)hpA, w1v.z, accA[6]);
                accB[6] = __dp4a((int)hpB, w1v.z, accB[6]);
                accA[7] = __dp4a((int)hpA, w1v.w, accA[7]);
                accB[7] = __dp4a((int)hpB, w1v.w, accB[7]);
            }
            {
                const int4 w2v = wp[2];
                accA[8]  = __dp4a((int)hpA, w2v.x, accA[8]);
                accB[8]  = __dp4a((int)hpB, w2v.x, accB[8]);
                accA[9]  = __dp4a((int)hpA, w2v.y, accA[9]);
                accB[9]  = __dp4a((int)hpB, w2v.y, accB[9]);
                accA[10] = __dp4a((int)hpA, w2v.z, accA[10]);
                accB[10] = __dp4a((int)hpB, w2v.z, accB[10]);
                accA[11] = __dp4a((int)hpA, w2v.w, accA[11]);
                accB[11] = __dp4a((int)hpB, w2v.w, accB[11]);
            }
            {
                const int4 w3v = wp[3];
                accA[12] = __dp4a((int)hpA, w3v.x, accA[12]);
                accB[12] = __dp4a((int)hpB, w3v.x, accB[12]);
                accA[13] = __dp4a((int)hpA, w3v.y, accA[13]);
                accB[13] = __dp4a((int)hpB, w3v.y, accB[13]);
                accA[14] = __dp4a((int)hpA, w3v.z, accA[14]);
                accB[14] = __dp4a((int)hpB, w3v.z, accB[14]);
                accA[15] = __dp4a((int)hpA, w3v.w, accA[15]);
                accB[15] = __dp4a((int)hpB, w3v.w, accB[15]);
            }
        }
        __syncthreads();          // compute(c) done before buffer re-staged
    }

    // ---- epilogue (scalars loaded fresh: zero loop reg cost) ----
    const float a1  = p_a1[0];
    const float a2  = p_a2[0];
    const float a3  = p_a3[0];
    const float wa1 = p_wa1[0];
    const float wa2 = p_wa2[0];
    const float inv_a2 = 1.0f / a2;
    const float inv_a3 = 1.0f / a3;
    const float s1scale = a1 * wa1;
    const float s2scale = a3 * wa2;

    float* outs = reinterpret_cast<float*>(xsq);   // idle after last barrier

#pragma unroll
    for (int half = 0; half < 2; ++half) {
        const int* acc = half ? accB : accA;
        const int  row = half ? rowB : rowA;

        unsigned sp[4];
        unsigned spacc = 0;
#pragma unroll
        for (int j = 0; j < 16; ++j) {
            const float h = __fmaf_rn((float)acc[j], s1scale, b1s[j]);
            const float sg = __fdividef(1.0f, 1.0f + __expf(-h));
            float u = sg * inv_a2;
            u = fminf(fmaxf(u, 0.0f), 255.0f);
            const float s = (float)__float2int_rn(u) * a2;      // post-sigmoid fq
            const float v2 = s * inv_a3;
            int s2q;
            asm("cvt.rni.sat.s8.f32 %0, %1;" : "=r"(s2q) : "f"(v2));
            spacc = __byte_perm(spacc, (unsigned)s2q, 0x4321);
            if ((j & 3) == 3) sp[j >> 2] = spacc;
        }
#pragma unroll
        for (int j = 0; j < 10; ++j) {
            int o = 0;
            o = __dp4a((int)sp[0], w2p[j * 4 + 0], o);
            o = __dp4a((int)sp[1], w2p[j * 4 + 1], o);
            o = __dp4a((int)sp[2], w2p[j * 4 + 2], o);
            o = __dp4a((int)sp[3], w2p[j * 4 + 3], o);
            outs[row * 10 + j] = __fmaf_rn((float)o, s2scale, b2s[j]);
        }
    }
    __syncthreads();

    // coalesced output store: 5120 contiguous floats per block
    const size_t obase = (size_t)row0 * 10;
#pragma unroll
    for (int t = 0; t < 20; ++t) {
        const int i = t * THREADS + tid;
        out[obase + i] = outs[i];
    }
}

extern "C" void kernel_launch(void* const* d_in, const int* in_sizes, int n_in,
                              void* d_out, int out_size)
{
    const float* x       = (const float*)d_in[0];
    const float* p_alpha = (const float*)d_in[1];
    const float* p_beta  = (const float*)d_in[2];
    const float* p_a1    = (const float*)d_in[3];
    const float* p_a2    = (const float*)d_in[4];
    const float* p_a3    = (const float*)d_in[5];
    const float* W1      = (const float*)d_in[6];
    const float* b1      = (const float*)d_in[7];
    const float* p_wa1   = (const float*)d_in[8];
    const float* W2      = (const float*)d_in[9];
    const float* b2      = (const float*)d_in[10];
    const float* p_wa2   = (const float*)d_in[11];
    float* out = (float*)d_out;

    const int M = in_sizes[0] / NCOLS;     // 262144
    const int blocks = M / RPB;            // 512

    net_quant_kernel<<<blocks, THREADS>>>(x, p_alpha, p_beta, p_a1, p_a2, p_a3,
                                          W1, b1, p_wa1, W2, b2, p_wa2, out);
}

// round 10
// speedup vs baseline: 1.7432x; 1.7432x over previous
#include <cuda_runtime.h>
#include <cstdint>
#include <cstddef>

// Net_quantize: fused MFL recurrence + LSQ fake-quant + 2 quantized linear layers.
// WARP-AUTONOMOUS version of the R6 winner: each warp cp.asyncs exactly the 32
// rows it consumes into its own smem region, so the main loop needs only
// __syncwarp (no CTA barriers -> no inter-warp convoy). Double-buffered,
// swizzled conflict-free layout. fc1/fc2 via DP4A on exact int8 levels.

#define THREADS 256
#define WARPS   8
#define NCOLS   128
#define NCHUNK  8             // 16 cols per chunk

__device__ __forceinline__ void cp_async16(uint32_t saddr, const void* gptr) {
    asm volatile("cp.async.cg.shared.global [%0], [%1], 16;"
                 :: "r"(saddr), "l"(gptr) : "memory");
}
__device__ __forceinline__ void cp_commit() {
    asm volatile("cp.async.commit_group;" ::: "memory");
}
template <int N>
__device__ __forceinline__ void cp_wait() {
    asm volatile("cp.async.wait_group %0;" :: "n"(N) : "memory");
}

__global__ __launch_bounds__(THREADS, 5)
void net_quant_kernel(const float* __restrict__ x,
                      const float* __restrict__ p_alpha,
                      const float* __restrict__ p_beta,
                      const float* __restrict__ p_a1,
                      const float* __restrict__ p_a2,
                      const float* __restrict__ p_a3,
                      const float* __restrict__ W1,
                      const float* __restrict__ b1,
                      const float* __restrict__ p_wa1,
                      const float* __restrict__ W2,
                      const float* __restrict__ b2,
                      const float* __restrict__ p_wa2,
                      float* __restrict__ out)
{
    // per-warp staging: [warp][buf][row(32)][slot(4)] float4 = 32 KiB total
    __shared__ float4 xw[WARPS][2][32][4];
    __shared__ int    w1p[32 * 16];       // [kc][j], kc = k/4
    __shared__ int    w2p[10 * 4];        // [j][c]
    __shared__ float  b1s[16];
    __shared__ float  b2s[10];

    const int tid  = threadIdx.x;
    const int wid  = tid >> 5;
    const int lane = tid & 31;
    const int row0 = blockIdx.x * THREADS;

    // staging lane geometry: lane stages quad q of rows r_base+{0,8,16,24}
    const int r_base = lane >> 2, q = lane & 3;
    const int slot_w = (q + (r_base >> 1)) & 3;        // same for all 4 rows (8k>>1 ≡ 0 mod 4)

    // global source: this warp owns rows row0 + wid*32 .. +31
    const float* gsrc = x + (size_t)(row0 + wid * 32 + r_base) * NCOLS + q * 4;
    const uint32_t xw_base = (uint32_t)__cvta_generic_to_shared(&xw[wid][0][0][0]);
    const uint32_t soff = (uint32_t)(r_base * 4 + slot_w) * 16u;   // bytes within buffer
    const uint32_t ROWB = 8 * 64u;                                  // 8 rows stride bytes
    const uint32_t BUFB = 32 * 64u;                                 // buffer stride bytes

    // ---- issue chunk 0 staging immediately ----
    {
        const uint32_t b = xw_base + soff;
        cp_async16(b,            gsrc);
        cp_async16(b + 1 * ROWB, gsrc + (size_t)8  * NCOLS);
        cp_async16(b + 2 * ROWB, gsrc + (size_t)16 * NCOLS);
        cp_async16(b + 3 * ROWB, gsrc + (size_t)24 * NCOLS);
        cp_commit();
    }

    const float alpha   = p_alpha[0];
    const float beta    = p_beta[0];
    const float inv_a1  = 1.0f / p_a1[0];

    // ---- quantize + pack W1 (16x128), layout [kc][j] ----
    {
        const float inv_wa1 = 1.0f / p_wa1[0];
        for (int i = tid; i < 512; i += THREADS) {
            const int kc = i >> 4, j = i & 15;
            unsigned v = 0;
#pragma unroll
            for (int b = 0; b < 4; ++b) {
                float t = W1[j * 128 + kc * 4 + b] * inv_wa1;
                int qq;
                asm("cvt.rni.sat.s8.f32 %0, %1;" : "=r"(qq) : "f"(t));
                v = __byte_perm(v, (unsigned)qq, 0x4321);
            }
            w1p[i] = (int)v;
        }
    }
    // ---- quantize + pack W2 (10x16), preload biases ----
    if (tid < 40) {
        const float inv_wa2 = 1.0f / p_wa2[0];
        const int j = tid >> 2, c = tid & 3;
        unsigned v = 0;
#pragma unroll
        for (int b = 0; b < 4; ++b) {
            float t = W2[j * 16 + c * 4 + b] * inv_wa2;
            int qq;
            asm("cvt.rni.sat.s8.f32 %0, %1;" : "=r"(qq) : "f"(t));
            v = __byte_perm(v, (unsigned)qq, 0x4321);
        }
        w2p[tid] = (int)v;
    }
    if (tid >= 64 && tid < 80) b1s[tid - 64] = b1[tid - 64];
    if (tid >= 96 && tid < 106) b2s[tid - 96] = b2[tid - 96];
    __syncthreads();            // the ONLY CTA barrier before the epilogue

    // ---- main loop: warp-autonomous, __syncwarp only ----
    float w = 1.0f;
    int acc[16];
#pragma unroll
    for (int j = 0; j < 16; ++j) acc[j] = 0;
    unsigned hp = 0;

    const int halfl = lane >> 1;

#pragma unroll
    for (int c = 0; c < NCHUNK; ++c) {
        if (c < NCHUNK - 1) {
            // stage chunk c+1 into the other buffer (its readers finished at
            // chunk c-1 and passed that iteration's trailing __syncwarp).
            const uint32_t b = xw_base + (((c + 1) & 1) ? BUFB : 0u) + soff;
            const float* g = gsrc + (c + 1) * 16;
            cp_async16(b,            g);
            cp_async16(b + 1 * ROWB, g + (size_t)8  * NCOLS);
            cp_async16(b + 2 * ROWB, g + (size_t)16 * NCOLS);
            cp_async16(b + 3 * ROWB, g + (size_t)24 * NCOLS);
            cp_commit();
            cp_wait<1>();       // own chunk-c copies complete (c+1 in flight)
        } else {
            cp_wait<0>();
        }
        __syncwarp();           // all lanes' chunk-c copies visible warp-wide

        // 16 recurrence steps + 4 dp4a groups; one swizzled LDS.128 per group
        const float4* xr = &xw[wid][c & 1][lane][0];
#pragma unroll
        for (int g4 = 0; g4 < 4; ++g4) {
            const int s = (g4 + halfl) & 3;
            const float4 v = xr[s];
            const float xe[4] = {v.x, v.y, v.z, v.w};
#pragma unroll
            for (int b = 0; b < 4; ++b) {
                // quantize w_k: clip+round-half-even == cvt.rni.sat.s8
                const float t = w * inv_a1;
                int hq;
                asm("cvt.rni.sat.s8.f32 %0, %1;" : "=r"(hq) : "f"(t));
                hp = __byte_perm(hp, (unsigned)hq, 0x4321);
                // w' = alpha*rcp(w) + (w - beta*x_k); t2 fma overlaps the MUFU
                const float t2 = __fmaf_rn(-beta, xe[b], w);
                float r;
                asm("rcp.approx.f32 %0, %1;" : "=f"(r) : "f"(w));
                w = __fmaf_rn(alpha, r, t2);
            }
            const int kc = c * 4 + g4;
            const int4* wp = reinterpret_cast<const int4*>(&w1p[kc * 16]);
            const int4 w0 = wp[0], w1v = wp[1], w2v = wp[2], w3v = wp[3];
            acc[0]  = __dp4a((int)hp, w0.x,  acc[0]);
            acc[1]  = __dp4a((int)hp, w0.y,  acc[1]);
            acc[2]  = __dp4a((int)hp, w0.z,  acc[2]);
            acc[3]  = __dp4a((int)hp, w0.w,  acc[3]);
            acc[4]  = __dp4a((int)hp, w1v.x, acc[4]);
            acc[5]  = __dp4a((int)hp, w1v.y, acc[5]);
            acc[6]  = __dp4a((int)hp, w1v.z, acc[6]);
            acc[7]  = __dp4a((int)hp, w1v.w, acc[7]);
            acc[8]  = __dp4a((int)hp, w2v.x, acc[8]);
            acc[9]  = __dp4a((int)hp, w2v.y, acc[9]);
            acc[10] = __dp4a((int)hp, w2v.z, acc[10]);
            acc[11] = __dp4a((int)hp, w2v.w, acc[11]);
            acc[12] = __dp4a((int)hp, w3v.x, acc[12]);
            acc[13] = __dp4a((int)hp, w3v.y, acc[13]);
            acc[14] = __dp4a((int)hp, w3v.z, acc[14]);
            acc[15] = __dp4a((int)hp, w3v.w, acc[15]);
        }
        __syncwarp();           // compute(c) done before buffer is re-staged
    }

    // ---- epilogue (scalars loaded fresh; warp-local output staging) ----
    const float a1  = p_a1[0];
    const float a2  = p_a2[0];
    const float a3  = p_a3[0];
    const float wa1 = p_wa1[0];
    const float wa2 = p_wa2[0];
    const float inv_a2 = 1.0f / a2;
    const float inv_a3 = 1.0f / a3;
    const float s1scale = a1 * wa1;
    const float s2scale = a3 * wa2;

    unsigned sp[4];
    unsigned spacc = 0;
#pragma unroll
    for (int j = 0; j < 16; ++j) {
        const float h = __fmaf_rn((float)acc[j], s1scale, b1s[j]);
        const float sg = __fdividef(1.0f, 1.0f + __expf(-h));
        float u = sg * inv_a2;
        u = fminf(fmaxf(u, 0.0f), 255.0f);
        const float s = (float)__float2int_rn(u) * a2;          // post-sigmoid fq
        const float v2 = s * inv_a3;
        int s2q;
        asm("cvt.rni.sat.s8.f32 %0, %1;" : "=r"(s2q) : "f"(v2)); // qAct3 level
        spacc = __byte_perm(spacc, (unsigned)s2q, 0x4321);
        if ((j & 3) == 3) sp[j >> 2] = spacc;
    }

    // warp-private staging region is idle after the trailing __syncwarp
    float* outs = reinterpret_cast<float*>(&xw[wid][0][0][0]);
#pragma unroll
    for (int j = 0; j < 10; ++j) {
        int o = 0;
        o = __dp4a((int)sp[0], w2p[j * 4 + 0], o);
        o = __dp4a((int)sp[1], w2p[j * 4 + 1], o);
        o = __dp4a((int)sp[2], w2p[j * 4 + 2], o);
        o = __dp4a((int)sp[3], w2p[j * 4 + 3], o);
        outs[lane * 10 + j] = __fmaf_rn((float)o, s2scale, b2s[j]);
    }
    __syncwarp();

    // coalesced per-warp store: 320 contiguous floats
    const size_t obase = (size_t)(row0 + wid * 32) * 10;
#pragma unroll
    for (int t = 0; t < 10; ++t) {
        const int i = t * 32 + lane;
        out[obase + i] = outs[i];
    }
}

extern "C" void kernel_launch(void* const* d_in, const int* in_sizes, int n_in,
                              void* d_out, int out_size)
{
    const float* x       = (const float*)d_in[0];
    const float* p_alpha = (const float*)d_in[1];
    const float* p_beta  = (const float*)d_in[2];
    const float* p_a1    = (const float*)d_in[3];
    const float* p_a2    = (const float*)d_in[4];
    const float* p_a3    = (const float*)d_in[5];
    const float* W1      = (const float*)d_in[6];
    const float* b1      = (const float*)d_in[7];
    const float* p_wa1   = (const float*)d_in[8];
    const float* W2      = (const float*)d_in[9];
    const float* b2      = (const float*)d_in[10];
    const float* p_wa2   = (const float*)d_in[11];
    float* out = (float*)d_out;

    const int M = in_sizes[0] / NCOLS;     // 262144
    const int blocks = M / THREADS;        // 1024

    net_quant_kernel<<<blocks, THREADS>>>(x, p_alpha, p_beta, p_a1, p_a2, p_a3,
                                          W1, b1, p_wa1, W2, b2, p_wa2, out);
}

// round 11
// speedup vs baseline: 1.7551x; 1.0068x over previous
#include <cuda_runtime.h>
#include <cstdint>
#include <cstddef>

// Net_quantize: fused MFL recurrence + LSQ fake-quant + 2 quantized linear layers.
// Warp-autonomous (R9 winner) + fc1 moved from per-thread DP4A to tensor-core
// IMMA: per warp fc1 is an m32 x n16 x k128 int8 GEMM done with
// mma.sync.m16n8k32.s8 (A = quantized recurrence levels staged via STS.128 +
// ldmatrix, B = pre-packed W1 fragments in smem). fc2 stays DP4A.

#define THREADS 256
#define WARPS   8
#define NCOLS   128
#define NCHUNK  8             // 16 cols per chunk; 1 k32 MMA block per 2 chunks

__device__ __forceinline__ void cp_async16(uint32_t saddr, const void* gptr) {
    asm volatile("cp.async.cg.shared.global [%0], [%1], 16;"
                 :: "r"(saddr), "l"(gptr) : "memory");
}
__device__ __forceinline__ void cp_commit() {
    asm volatile("cp.async.commit_group;" ::: "memory");
}
template <int N>
__device__ __forceinline__ void cp_wait() {
    asm volatile("cp.async.wait_group %0;" :: "n"(N) : "memory");
}

__global__ __launch_bounds__(THREADS, 5)
void net_quant_kernel(const float* __restrict__ x,
                      const float* __restrict__ p_alpha,
                      const float* __restrict__ p_beta,
                      const float* __restrict__ p_a1,
                      const float* __restrict__ p_a2,
                      const float* __restrict__ p_a3,
                      const float* __restrict__ W1,
                      const float* __restrict__ b1,
                      const float* __restrict__ p_wa1,
                      const float* __restrict__ W2,
                      const float* __restrict__ b2,
                      const float* __restrict__ p_wa2,
                      float* __restrict__ out)
{
    // per-warp x staging: [warp][buf][row(32)][slot(4)] float4 = 32 KiB
    __shared__ float4 xw[WARPS][2][32][4];
    // W1 int8 B-fragments: [kt(4)][nt(2)][lane(32)][r(2)] = 2 KiB
    __shared__ int    w1B[4][2][32][2];
    __shared__ int    w2p[10 * 4];
    __shared__ float  b1s[16];
    __shared__ float  b2s[10];
    // per-warp hq tile: 32 rows x 32 bytes (k32), half-swizzled = 1 KiB/warp
    __shared__ uint4  sAq[WARPS][64];

    const int tid  = threadIdx.x;
    const int wid  = tid >> 5;
    const int lane = tid & 31;
    const int row0 = blockIdx.x * THREADS;

    // x staging geometry (identical to R9): lane stages quad q of rows r_base+{0,8,16,24}
    const int r_base = lane >> 2, q = lane & 3;
    const int slot_w = (q + (r_base >> 1)) & 3;
    const float* gsrc = x + (size_t)(row0 + wid * 32 + r_base) * NCOLS + q * 4;
    const uint32_t xw_base = (uint32_t)__cvta_generic_to_shared(&xw[wid][0][0][0]);
    const uint32_t soff = (uint32_t)(r_base * 4 + slot_w) * 16u;
    const uint32_t ROWB = 8 * 64u;
    const uint32_t BUFB = 32 * 64u;

    // ---- issue chunk 0 staging immediately ----
    {
        const uint32_t b = xw_base + soff;
        cp_async16(b,            gsrc);
        cp_async16(b + 1 * ROWB, gsrc + (size_t)8  * NCOLS);
        cp_async16(b + 2 * ROWB, gsrc + (size_t)16 * NCOLS);
        cp_async16(b + 3 * ROWB, gsrc + (size_t)24 * NCOLS);
        cp_commit();
    }

    const float alpha  = p_alpha[0];
    const float beta   = p_beta[0];
    const float inv_a1 = 1.0f / p_a1[0];

    // ---- quantize W1 into per-lane B fragments ----
    // word widx: lane=widx&31, r=(widx>>5)&1, nt=(widx>>6)&1, kt=widx>>7
    // holds W1q[j = nt*8 + (lane>>2)][k0 = kt*32 + r*16 + 4*(lane&3) .. +3]
    {
        const float inv_wa1 = 1.0f / p_wa1[0];
#pragma unroll
        for (int widx = 2 * tid; widx <= 2 * tid + 1; ++widx) {
            const int ln = widx & 31, r = (widx >> 5) & 1;
            const int nt = (widx >> 6) & 1, kt = widx >> 7;
            const int j  = nt * 8 + (ln >> 2);
            const int k0 = kt * 32 + r * 16 + 4 * (ln & 3);
            unsigned v = 0;
#pragma unroll
            for (int b = 0; b < 4; ++b) {
                float t = W1[j * 128 + k0 + b] * inv_wa1;
                int qq;
                asm("cvt.rni.sat.s8.f32 %0, %1;" : "=r"(qq) : "f"(t));
                v = __byte_perm(v, (unsigned)qq, 0x4321);
            }
            w1B[kt][nt][ln][r] = (int)v;
        }
    }
    // ---- quantize + pack W2 (10x16), preload biases ----
    if (tid < 40) {
        const float inv_wa2 = 1.0f / p_wa2[0];
        const int j = tid >> 2, c = tid & 3;
        unsigned v = 0;
#pragma unroll
        for (int b = 0; b < 4; ++b) {
            float t = W2[j * 16 + c * 4 + b] * inv_wa2;
            int qq;
            asm("cvt.rni.sat.s8.f32 %0, %1;" : "=r"(qq) : "f"(t));
            v = __byte_perm(v, (unsigned)qq, 0x4321);
        }
        w2p[tid] = (int)v;
    }
    if (tid >= 64 && tid < 80) b1s[tid - 64] = b1[tid - 64];
    if (tid >= 96 && tid < 106) b2s[tid - 96] = b2[tid - 96];
    __syncthreads();            // the ONLY CTA barrier before the epilogue

    // ---- main loop ----
    float w = 1.0f;
    unsigned hp = 0;
    // acc[mt*2+nt][r]: D of mma tile (rows mt*16+.., cols nt*8+..)
    int acc[4][4];
#pragma unroll
    for (int t1 = 0; t1 < 4; ++t1)
#pragma unroll
        for (int t2 = 0; t2 < 4; ++t2) acc[t1][t2] = 0;

    const int halfl = lane >> 1;
    const uint32_t sA_base = (uint32_t)__cvta_generic_to_shared(&sAq[wid][0]);

#pragma unroll
    for (int c = 0; c < NCHUNK; ++c) {
        if (c < NCHUNK - 1) {
            const uint32_t b = xw_base + (((c + 1) & 1) ? BUFB : 0u) + soff;
            const float* g = gsrc + (c + 1) * 16;
            cp_async16(b,            g);
            cp_async16(b + 1 * ROWB, g + (size_t)8  * NCOLS);
            cp_async16(b + 2 * ROWB, g + (size_t)16 * NCOLS);
            cp_async16(b + 3 * ROWB, g + (size_t)24 * NCOLS);
            cp_commit();
            cp_wait<1>();
        } else {
            cp_wait<0>();
        }
        __syncwarp();   // chunk-c x visible; also orders prior ldmatrix reads
                        // before this iteration's sA overwrite

        // 16 recurrence steps -> 4 packed hq words
        const float4* xr = &xw[wid][c & 1][lane][0];
        unsigned hpv[4];
#pragma unroll
        for (int g4 = 0; g4 < 4; ++g4) {
            const int s = (g4 + halfl) & 3;
            const float4 v = xr[s];
            const float xe[4] = {v.x, v.y, v.z, v.w};
#pragma unroll
            for (int b = 0; b < 4; ++b) {
                const float t = w * inv_a1;
                int hq;
                asm("cvt.rni.sat.s8.f32 %0, %1;" : "=r"(hq) : "f"(t));
                hp = __byte_perm(hp, (unsigned)hq, 0x4321);
                const float t2 = __fmaf_rn(-beta, xe[b], w);
                float r;
                asm("rcp.approx.f32 %0, %1;" : "=f"(r) : "f"(w));
                w = __fmaf_rn(alpha, r, t2);
            }
            hpv[g4] = hp;
        }
        // store this k16 half of the warp's A tile (conflict-free STS.128)
        {
            const uint32_t haddr = sA_base + (uint32_t)(lane * 32)
                                 + 16u * (unsigned)((c & 1) ^ ((lane >> 2) & 1));
            asm volatile("st.shared.v4.b32 [%0], {%1,%2,%3,%4};"
                         :: "r"(haddr), "r"(hpv[0]), "r"(hpv[1]),
                            "r"(hpv[2]), "r"(hpv[3]) : "memory");
        }

        if (c & 1) {            // full k32 staged -> 2 ldmatrix + 4 mma
            __syncwarp();
            const int kt = c >> 1;
#pragma unroll
            for (int mt = 0; mt < 2; ++mt) {
                const int rowg = mt * 16 + (lane & 15);
                const uint32_t la = sA_base + (uint32_t)(rowg * 32)
                                  + 16u * (unsigned)((lane >> 4) ^ ((rowg >> 2) & 1));
                unsigned a0, a1, a2, a3;
                asm volatile("ldmatrix.sync.aligned.m8n8.x4.shared.b16 "
                             "{%0,%1,%2,%3}, [%4];"
                             : "=r"(a0), "=r"(a1), "=r"(a2), "=r"(a3) : "r"(la));
#pragma unroll
                for (int nt = 0; nt < 2; ++nt) {
                    const int2 bb = *reinterpret_cast<const int2*>(&w1B[kt][nt][lane][0]);
                    asm volatile("mma.sync.aligned.m16n8k32.row.col.s32.s8.s8.s32 "
                                 "{%0,%1,%2,%3}, {%4,%5,%6,%7}, {%8,%9}, {%0,%1,%2,%3};"
                                 : "+r"(acc[mt * 2 + nt][0]), "+r"(acc[mt * 2 + nt][1]),
                                   "+r"(acc[mt * 2 + nt][2]), "+r"(acc[mt * 2 + nt][3])
                                 : "r"(a0), "r"(a1), "r"(a2), "r"(a3),
                                   "r"(bb.x), "r"(bb.y));
                }
            }
        }
    }
    __syncwarp();               // last ldmatrix reads done before sA reuse below

    // ---- epilogue ----
    const float a1  = p_a1[0];
    const float a2  = p_a2[0];
    const float a3  = p_a3[0];
    const float wa1 = p_wa1[0];
    const float wa2 = p_wa2[0];
    const float inv_a2 = 1.0f / a2;
    const float inv_a3 = 1.0f / a3;
    const float s1scale = a1 * wa1;
    const float s2scale = a3 * wa2;

    // scatter quantized s8 levels into sS[32 rows][16 cols] (reuses sA region)
#pragma unroll
    for (int mt = 0; mt < 2; ++mt) {
#pragma unroll
        for (int nt = 0; nt < 2; ++nt) {
#pragma unroll
            for (int rp = 0; rp < 2; ++rp) {
                const int row = mt * 16 + (lane >> 2) + 8 * rp;
                const int colb = nt * 8 + 2 * (lane & 3);
                unsigned pair = 0;
#pragma unroll
                for (int rr = 0; rr < 2; ++rr) {
                    const int d = acc[mt * 2 + nt][2 * rp + rr];
                    const float h = __fmaf_rn((float)d, s1scale, b1s[colb + rr]);
                    const float sg = __fdividef(1.0f, 1.0f + __expf(-h));
                    float u = sg * inv_a2;
                    u = fminf(fmaxf(u, 0.0f), 255.0f);
                    const float sv = (float)__float2int_rn(u) * a2;
                    const float v2 = sv * inv_a3;
                    int s2q;
                    asm("cvt.rni.sat.s8.f32 %0, %1;" : "=r"(s2q) : "f"(v2));
                    pair |= ((unsigned)s2q & 0xffu) << (8 * rr);
                }
                const uint32_t sa = sA_base + (uint32_t)(row * 16 + colb);
                asm volatile("st.shared.u16 [%0], %1;"
                             :: "r"(sa), "h"((unsigned short)pair) : "memory");
            }
        }
    }
    __syncwarp();

    // fc2: thread = row again
    int4 sp;
    {
        const uint32_t sa = sA_base + (uint32_t)(lane * 16);
        asm volatile("ld.shared.v4.b32 {%0,%1,%2,%3}, [%4];"
                     : "=r"(sp.x), "=r"(sp.y), "=r"(sp.z), "=r"(sp.w) : "r"(sa));
    }

    // output staging reuses this warp's xw region (idle after last chunk)
    float* outs = reinterpret_cast<float*>(&xw[wid][0][0][0]);
#pragma unroll
    for (int j = 0; j < 10; ++j) {
        int o = 0;
        o = __dp4a(sp.x, w2p[j * 4 + 0], o);
        o = __dp4a(sp.y, w2p[j * 4 + 1], o);
        o = __dp4a(sp.z, w2p[j * 4 + 2], o);
        o = __dp4a(sp.w, w2p[j * 4 + 3], o);
        outs[lane * 10 + j] = __fmaf_rn((float)o, s2scale, b2s[j]);
    }
    __syncwarp();

    // coalesced per-warp store: 320 contiguous floats
    const size_t obase = (size_t)(row0 + wid * 32) * 10;
#pragma unroll
    for (int t = 0; t < 10; ++t) {
        const int i = t * 32 + lane;
        out[obase + i] = outs[i];
    }
}

extern "C" void kernel_launch(void* const* d_in, const int* in_sizes, int n_in,
                              void* d_out, int out_size)
{
    const float* x       = (const float*)d_in[0];
    const float* p_alpha = (const float*)d_in[1];
    const float* p_beta  = (const float*)d_in[2];
    const float* p_a1    = (const float*)d_in[3];
    const float* p_a2    = (const float*)d_in[4];
    const float* p_a3    = (const float*)d_in[5];
    const float* W1      = (const float*)d_in[6];
    const float* b1      = (const float*)d_in[7];
    const float* p_wa1   = (const float*)d_in[8];
    const float* W2      = (const float*)d_in[9];
    const float* b2      = (const float*)d_in[10];
    const float* p_wa2   = (const float*)d_in[11];
    float* out = (float*)d_out;

    const int M = in_sizes[0] / NCOLS;     // 262144
    const int blocks = M / THREADS;        // 1024

    net_quant_kernel<<<blocks, THREADS>>>(x, p_alpha, p_beta, p_a1, p_a2, p_a3,
                                          W1, b1, p_wa1, W2, b2, p_wa2, out);
}